// round 12
// baseline (speedup 1.0000x reference)
#include <cuda_runtime.h>
#include <cstdint>

#define N_NODES 100000
#define DIM 64
#define N_EDGES 1000000
#define N_GRAPHS 256
#define OUT_DIM 10
#define FEAT (N_NODES * DIM)
#define BN_EPS 1e-5f

// ---------------- scratch (no allocation allowed) ----------------
__device__ float g_X[FEAT];            // node features between layers
__device__ float g_AGG[FEAT];          // (1+eps)*x + scatter-add target
__device__ float g_STATS[2 * DIM];     // column sums / sumsq for BN
__device__ float g_POOL[N_GRAPHS * DIM];
__device__ float g_CNT[N_GRAPHS];

// ---------------- layer 0: AGG = (1+eps0)*x ----------------
__global__ void k_init(const float4* __restrict__ x, const float* __restrict__ eps_g) {
    int i = blockIdx.x * blockDim.x + threadIdx.x;
    float ep = 1.0f + eps_g[0];
    if (i < FEAT / 4) {
        float4 v = x[i];
        v.x *= ep; v.y *= ep; v.z *= ep; v.w *= ep;
        reinterpret_cast<float4*>(g_AGG)[i] = v;
    }
}

// ---------------- scatter-add: AGG[dst] += x[src] ----------------
// 16 threads per edge, one float4 vector-red each. Also zeroes the BN stats
// (and pool buffers on the last layer) — this kernel never reads them.
__global__ void k_scatter(const float* __restrict__ xin, int use_in,
                          const int* __restrict__ src, const int* __restrict__ dst,
                          int zero_pool) {
    if (blockIdx.x == 0 && threadIdx.x < 2 * DIM) g_STATS[threadIdx.x] = 0.0f;
    if (zero_pool && blockIdx.x == 1) {
        for (int i = threadIdx.x; i < N_GRAPHS * DIM; i += blockDim.x) g_POOL[i] = 0.0f;
        for (int i = threadIdx.x; i < N_GRAPHS; i += blockDim.x) g_CNT[i] = 0.0f;
    }
    const float* x = use_in ? xin : g_X;
    int gid = blockIdx.x * blockDim.x + threadIdx.x;
    int e = gid >> 4;
    int q = gid & 15;
    if (e < N_EDGES) {
        int s = __ldg(src + e);
        int d = __ldg(dst + e);
        float4 v = *reinterpret_cast<const float4*>(x + (size_t)s * DIM + q * 4);
        float* p = g_AGG + (size_t)d * DIM + q * 4;
        asm volatile("red.global.add.v4.f32 [%0], {%1,%2,%3,%4};"
                     :: "l"(p), "f"(v.x), "f"(v.y), "f"(v.z), "f"(v.w) : "memory");
    }
}

// ---------------- fused 2x(GEMM 64x64 + bias + relu) + BN stats ----------------
// One row per thread, 64 rows per block. Inputs staged in smem (stride 65 ->
// conflict-free). Weights in smem, read as broadcast LDS.128, consumed by
// packed fma.rn.f32x2 (2 fp32 FMA / instruction).
__device__ __forceinline__ void gemm_row(const float* __restrict__ in_row,
                                         const ulonglong2* __restrict__ wp,
                                         const float* __restrict__ bias,
                                         unsigned long long acc[32]) {
#pragma unroll
    for (int j = 0; j < 32; j++)
        asm("mov.b64 %0, {%1,%2};" : "=l"(acc[j]) : "f"(bias[2 * j]), "f"(bias[2 * j + 1]));
#pragma unroll 4
    for (int k = 0; k < DIM; k++) {
        float v = in_row[k];
        unsigned long long vv;
        asm("mov.b64 %0, {%1,%1};" : "=l"(vv) : "f"(v));
#pragma unroll
        for (int q = 0; q < 16; q++) {
            ulonglong2 w = wp[k * 16 + q];
            asm("fma.rn.f32x2 %0, %1, %2, %0;" : "+l"(acc[2 * q])     : "l"(vv), "l"(w.x));
            asm("fma.rn.f32x2 %0, %1, %2, %0;" : "+l"(acc[2 * q + 1]) : "l"(vv), "l"(w.y));
        }
    }
}

#define MLP_ROWS 64
#define SPITCH (DIM + 1)

__global__ __launch_bounds__(MLP_ROWS)
void k_mlp(const float* __restrict__ w1, const float* __restrict__ b1,
           const float* __restrict__ w2, const float* __restrict__ b2) {
    __shared__ float  s_in[MLP_ROWS * SPITCH];
    __shared__ float4 s_w[DIM * DIM / 4];
    __shared__ float  s_b[DIM];

    int tid  = threadIdx.x;
    int base = blockIdx.x * MLP_ROWS;
    int row  = base + tid;

    // stage 64 input rows (coalesced float4 loads)
    for (int i = tid; i < MLP_ROWS * DIM / 4; i += MLP_ROWS) {
        int r = i >> 4, c4 = i & 15;
        float4 v = (base + r < N_NODES)
                       ? reinterpret_cast<const float4*>(g_AGG)[(size_t)base * 16 + i]
                       : make_float4(0.f, 0.f, 0.f, 0.f);
        float* p = &s_in[r * SPITCH + c4 * 4];
        p[0] = v.x; p[1] = v.y; p[2] = v.z; p[3] = v.w;
    }
    for (int i = tid; i < DIM * DIM / 4; i += MLP_ROWS)
        s_w[i] = reinterpret_cast<const float4*>(w1)[i];
    if (tid < DIM) s_b[tid] = b1[tid];
    __syncthreads();

    unsigned long long acc[32];
    const ulonglong2* wp = reinterpret_cast<const ulonglong2*>(s_w);

    // GEMM1 + relu -> own smem row (only this thread touches its row)
    gemm_row(&s_in[tid * SPITCH], wp, s_b, acc);
#pragma unroll
    for (int j = 0; j < 32; j++) {
        float lo, hi;
        asm("mov.b64 {%0,%1}, %2;" : "=f"(lo), "=f"(hi) : "l"(acc[j]));
        s_in[tid * SPITCH + 2 * j]     = fmaxf(lo, 0.f);
        s_in[tid * SPITCH + 2 * j + 1] = fmaxf(hi, 0.f);
    }
    __syncthreads();  // everyone done with w1 before overwrite

    for (int i = tid; i < DIM * DIM / 4; i += MLP_ROWS)
        s_w[i] = reinterpret_cast<const float4*>(w2)[i];
    if (tid < DIM) s_b[tid] = b2[tid];
    __syncthreads();

    // GEMM2 + relu; invalid rows must contribute exact zeros to BN stats
    gemm_row(&s_in[tid * SPITCH], wp, s_b, acc);
    bool valid = (row < N_NODES);
#pragma unroll
    for (int j = 0; j < 32; j++) {
        float lo, hi;
        asm("mov.b64 {%0,%1}, %2;" : "=f"(lo), "=f"(hi) : "l"(acc[j]));
        s_in[tid * SPITCH + 2 * j]     = valid ? fmaxf(lo, 0.f) : 0.f;
        s_in[tid * SPITCH + 2 * j + 1] = valid ? fmaxf(hi, 0.f) : 0.f;
    }
    __syncthreads();

    // coalesced writeback of h2
    for (int i = tid; i < MLP_ROWS * DIM / 4; i += MLP_ROWS) {
        int r = i >> 4, c4 = i & 15;
        if (base + r < N_NODES) {
            float* p = &s_in[r * SPITCH + c4 * 4];
            reinterpret_cast<float4*>(g_X)[(size_t)base * 16 + i] =
                make_float4(p[0], p[1], p[2], p[3]);
        }
    }

    // BN partial stats: thread tid owns column tid
    float s = 0.f, s2 = 0.f;
#pragma unroll 8
    for (int r = 0; r < MLP_ROWS; r++) {
        float v = s_in[r * SPITCH + tid];
        s += v; s2 += v * v;
    }
    atomicAdd(&g_STATS[tid], s);
    atomicAdd(&g_STATS[DIM + tid], s2);
}

// ---------------- BN apply + relu + next-layer (1+eps)*x init ----------------
__global__ void k_bn_init(const float* __restrict__ gamma, const float* __restrict__ beta,
                          const float* __restrict__ eps_g, int next_layer) {
    __shared__ float sc[DIM], sh[DIM];
    int tid = threadIdx.x;
    if (tid < DIM) {
        float mean = g_STATS[tid] * (1.0f / N_NODES);
        float var  = g_STATS[DIM + tid] * (1.0f / N_NODES) - mean * mean;
        float s    = gamma[tid] * rsqrtf(var + BN_EPS);
        sc[tid] = s;
        sh[tid] = beta[tid] - mean * s;
    }
    __syncthreads();
    float ep = 1.0f + eps_g[next_layer];
    int i = blockIdx.x * blockDim.x + tid;
    if (i < FEAT / 4) {
        float4 v = reinterpret_cast<const float4*>(g_X)[i];
        int c = (i & 15) * 4;
        v.x = fmaxf(v.x * sc[c]     + sh[c],     0.f);
        v.y = fmaxf(v.y * sc[c + 1] + sh[c + 1], 0.f);
        v.z = fmaxf(v.z * sc[c + 2] + sh[c + 2], 0.f);
        v.w = fmaxf(v.w * sc[c + 3] + sh[c + 3], 0.f);
        reinterpret_cast<float4*>(g_X)[i] = v;
        float4 a = make_float4(ep * v.x, ep * v.y, ep * v.z, ep * v.w);
        reinterpret_cast<float4*>(g_AGG)[i] = a;
    }
}

// ---------------- last layer: BN apply + relu + mean-pool accumulate ----------------
__global__ void k_bn_pool(const float* __restrict__ gamma, const float* __restrict__ beta,
                          const int* __restrict__ batch) {
    __shared__ float sc[DIM], sh[DIM];
    int tid = threadIdx.x;
    if (tid < DIM) {
        float mean = g_STATS[tid] * (1.0f / N_NODES);
        float var  = g_STATS[DIM + tid] * (1.0f / N_NODES) - mean * mean;
        float s    = gamma[tid] * rsqrtf(var + BN_EPS);
        sc[tid] = s;
        sh[tid] = beta[tid] - mean * s;
    }
    __syncthreads();
    int i = blockIdx.x * blockDim.x + tid;
    if (i < FEAT / 4) {
        int row = i >> 4;
        int g = __ldg(batch + row);
        float4 v = reinterpret_cast<const float4*>(g_X)[i];
        int c = (i & 15) * 4;
        v.x = fmaxf(v.x * sc[c]     + sh[c],     0.f);
        v.y = fmaxf(v.y * sc[c + 1] + sh[c + 1], 0.f);
        v.z = fmaxf(v.z * sc[c + 2] + sh[c + 2], 0.f);
        v.w = fmaxf(v.w * sc[c + 3] + sh[c + 3], 0.f);
        float* p = &g_POOL[g * DIM + c];
        asm volatile("red.global.add.v4.f32 [%0], {%1,%2,%3,%4};"
                     :: "l"(p), "f"(v.x), "f"(v.y), "f"(v.z), "f"(v.w) : "memory");
        if ((i & 15) == 0) atomicAdd(&g_CNT[g], 1.0f);
    }
}

// ---------------- head: out = (pool/cnt) @ lin_w + lin_b ----------------
__global__ void k_out(const float* __restrict__ lin_w, const float* __restrict__ lin_b,
                      float* __restrict__ out) {
    int gid = blockIdx.x * blockDim.x + threadIdx.x;
    if (gid < N_GRAPHS * OUT_DIM) {
        int g = gid / OUT_DIM, o = gid % OUT_DIM;
        float inv = 1.0f / fmaxf(g_CNT[g], 1.0f);
        float acc = lin_b[o];
#pragma unroll
        for (int c = 0; c < DIM; c++)
            acc += g_POOL[g * DIM + c] * inv * lin_w[c * OUT_DIM + o];
        out[gid] = acc;
    }
}

// ---------------- launch ----------------
extern "C" void kernel_launch(void* const* d_in, const int* in_sizes, int n_in,
                              void* d_out, int out_size) {
    const float* x     = (const float*)d_in[0];
    const int*   ei    = (const int*)d_in[1];
    const int*   batch = (const int*)d_in[2];
    const float* w1    = (const float*)d_in[3];
    const float* b1    = (const float*)d_in[4];
    const float* w2    = (const float*)d_in[5];
    const float* b2    = (const float*)d_in[6];
    const float* gamma = (const float*)d_in[7];
    const float* beta  = (const float*)d_in[8];
    const float* eps_g = (const float*)d_in[9];
    const float* lin_w = (const float*)d_in[10];
    const float* lin_b = (const float*)d_in[11];
    float* out = (float*)d_out;

    const int* src = ei;             // edge_index[0]
    const int* dst = ei + N_EDGES;   // edge_index[1]

    k_init<<<FEAT / 4 / 256, 256>>>((const float4*)x, eps_g);

    for (int l = 0; l < 3; l++) {
        k_scatter<<<(N_EDGES * 16) / 256, 256>>>(x, l == 0 ? 1 : 0, src, dst, l == 2 ? 1 : 0);
        k_mlp<<<(N_NODES + MLP_ROWS - 1) / MLP_ROWS, MLP_ROWS>>>(
            w1 + l * DIM * DIM, b1 + l * DIM, w2 + l * DIM * DIM, b2 + l * DIM);
        if (l < 2)
            k_bn_init<<<FEAT / 4 / 256, 256>>>(gamma + l * DIM, beta + l * DIM, eps_g, l + 1);
        else
            k_bn_pool<<<FEAT / 4 / 256, 256>>>(gamma + l * DIM, beta + l * DIM, batch);
    }

    k_out<<<(N_GRAPHS * OUT_DIM + 255) / 256, 256>>>(lin_w, lin_b, out);
}

// round 13
// speedup vs baseline: 1.0008x; 1.0008x over previous
#include <cuda_runtime.h>
#include <cstdint>

#define N_NODES 100000
#define DIM 64
#define N_EDGES 1000000
#define N_GRAPHS 256
#define OUT_DIM 10
#define FEAT (N_NODES * DIM)
#define BN_EPS 1e-5f

// ---------------- scratch (no allocation allowed) ----------------
__device__ float g_X[FEAT];            // node features between layers
__device__ float g_AGG[FEAT];          // (1+eps)*x + scatter-add target
__device__ float g_STATS[2 * DIM];     // column sums / sumsq for BN
__device__ float g_POOL[N_GRAPHS * DIM];
__device__ float g_CNT[N_GRAPHS];

// ---------------- layer 0: AGG = (1+eps0)*x ----------------
__global__ void k_init(const float4* __restrict__ x, const float* __restrict__ eps_g) {
    int i = blockIdx.x * blockDim.x + threadIdx.x;
    float ep = 1.0f + eps_g[0];
    if (i < FEAT / 4) {
        float4 v = x[i];
        v.x *= ep; v.y *= ep; v.z *= ep; v.w *= ep;
        reinterpret_cast<float4*>(g_AGG)[i] = v;
    }
}

// ---------------- scatter-add: AGG[dst] += x[src] ----------------
// 16 threads per edge, one float4 vector-red each. Also zeroes the BN stats
// (and pool buffers on the last layer) — this kernel never reads them.
__global__ void k_scatter(const float* __restrict__ xin, int use_in,
                          const int* __restrict__ src, const int* __restrict__ dst,
                          int zero_pool) {
    if (blockIdx.x == 0 && threadIdx.x < 2 * DIM) g_STATS[threadIdx.x] = 0.0f;
    if (zero_pool && blockIdx.x == 1) {
        for (int i = threadIdx.x; i < N_GRAPHS * DIM; i += blockDim.x) g_POOL[i] = 0.0f;
        for (int i = threadIdx.x; i < N_GRAPHS; i += blockDim.x) g_CNT[i] = 0.0f;
    }
    const float* x = use_in ? xin : g_X;
    int gid = blockIdx.x * blockDim.x + threadIdx.x;
    int e = gid >> 4;
    int q = gid & 15;
    if (e < N_EDGES) {
        int s = __ldg(src + e);
        int d = __ldg(dst + e);
        float4 v = *reinterpret_cast<const float4*>(x + (size_t)s * DIM + q * 4);
        float* p = g_AGG + (size_t)d * DIM + q * 4;
        asm volatile("red.global.add.v4.f32 [%0], {%1,%2,%3,%4};"
                     :: "l"(p), "f"(v.x), "f"(v.y), "f"(v.z), "f"(v.w) : "memory");
    }
}

// ---------------- fused 2x(GEMM 64x64 + bias + relu) + BN stats ----------------
// One row per thread, 64 rows per block. Inputs staged in smem (stride 65 ->
// conflict-free). Weights in smem, read as broadcast LDS.128, consumed by
// packed fma.rn.f32x2 (2 fp32 FMA / instruction).
__device__ __forceinline__ void gemm_row(const float* __restrict__ in_row,
                                         const ulonglong2* __restrict__ wp,
                                         const float* __restrict__ bias,
                                         unsigned long long acc[32]) {
#pragma unroll
    for (int j = 0; j < 32; j++)
        asm("mov.b64 %0, {%1,%2};" : "=l"(acc[j]) : "f"(bias[2 * j]), "f"(bias[2 * j + 1]));
#pragma unroll 4
    for (int k = 0; k < DIM; k++) {
        float v = in_row[k];
        unsigned long long vv;
        asm("mov.b64 %0, {%1,%1};" : "=l"(vv) : "f"(v));
#pragma unroll
        for (int q = 0; q < 16; q++) {
            ulonglong2 w = wp[k * 16 + q];
            asm("fma.rn.f32x2 %0, %1, %2, %0;" : "+l"(acc[2 * q])     : "l"(vv), "l"(w.x));
            asm("fma.rn.f32x2 %0, %1, %2, %0;" : "+l"(acc[2 * q + 1]) : "l"(vv), "l"(w.y));
        }
    }
}

#define MLP_ROWS 64
#define SPITCH (DIM + 1)

__global__ __launch_bounds__(MLP_ROWS)
void k_mlp(const float* __restrict__ w1, const float* __restrict__ b1,
           const float* __restrict__ w2, const float* __restrict__ b2) {
    __shared__ float  s_in[MLP_ROWS * SPITCH];
    __shared__ float4 s_w[DIM * DIM / 4];
    __shared__ float  s_b[DIM];

    int tid  = threadIdx.x;
    int base = blockIdx.x * MLP_ROWS;
    int row  = base + tid;

    // stage 64 input rows (coalesced float4 loads)
    for (int i = tid; i < MLP_ROWS * DIM / 4; i += MLP_ROWS) {
        int r = i >> 4, c4 = i & 15;
        float4 v = (base + r < N_NODES)
                       ? reinterpret_cast<const float4*>(g_AGG)[(size_t)base * 16 + i]
                       : make_float4(0.f, 0.f, 0.f, 0.f);
        float* p = &s_in[r * SPITCH + c4 * 4];
        p[0] = v.x; p[1] = v.y; p[2] = v.z; p[3] = v.w;
    }
    for (int i = tid; i < DIM * DIM / 4; i += MLP_ROWS)
        s_w[i] = reinterpret_cast<const float4*>(w1)[i];
    if (tid < DIM) s_b[tid] = b1[tid];
    __syncthreads();

    unsigned long long acc[32];
    const ulonglong2* wp = reinterpret_cast<const ulonglong2*>(s_w);

    // GEMM1 + relu -> own smem row (only this thread touches its row)
    gemm_row(&s_in[tid * SPITCH], wp, s_b, acc);
#pragma unroll
    for (int j = 0; j < 32; j++) {
        float lo, hi;
        asm("mov.b64 {%0,%1}, %2;" : "=f"(lo), "=f"(hi) : "l"(acc[j]));
        s_in[tid * SPITCH + 2 * j]     = fmaxf(lo, 0.f);
        s_in[tid * SPITCH + 2 * j + 1] = fmaxf(hi, 0.f);
    }
    __syncthreads();  // everyone done with w1 before overwrite

    for (int i = tid; i < DIM * DIM / 4; i += MLP_ROWS)
        s_w[i] = reinterpret_cast<const float4*>(w2)[i];
    if (tid < DIM) s_b[tid] = b2[tid];
    __syncthreads();

    // GEMM2 + relu; invalid rows must contribute exact zeros to BN stats
    gemm_row(&s_in[tid * SPITCH], wp, s_b, acc);
    bool valid = (row < N_NODES);
#pragma unroll
    for (int j = 0; j < 32; j++) {
        float lo, hi;
        asm("mov.b64 {%0,%1}, %2;" : "=f"(lo), "=f"(hi) : "l"(acc[j]));
        s_in[tid * SPITCH + 2 * j]     = valid ? fmaxf(lo, 0.f) : 0.f;
        s_in[tid * SPITCH + 2 * j + 1] = valid ? fmaxf(hi, 0.f) : 0.f;
    }
    __syncthreads();

    // coalesced writeback of h2
    for (int i = tid; i < MLP_ROWS * DIM / 4; i += MLP_ROWS) {
        int r = i >> 4, c4 = i & 15;
        if (base + r < N_NODES) {
            float* p = &s_in[r * SPITCH + c4 * 4];
            reinterpret_cast<float4*>(g_X)[(size_t)base * 16 + i] =
                make_float4(p[0], p[1], p[2], p[3]);
        }
    }

    // BN partial stats: thread tid owns column tid
    float s = 0.f, s2 = 0.f;
#pragma unroll 8
    for (int r = 0; r < MLP_ROWS; r++) {
        float v = s_in[r * SPITCH + tid];
        s += v; s2 += v * v;
    }
    atomicAdd(&g_STATS[tid], s);
    atomicAdd(&g_STATS[DIM + tid], s2);
}

// ---------------- BN apply + relu + next-layer (1+eps)*x init ----------------
__global__ void k_bn_init(const float* __restrict__ gamma, const float* __restrict__ beta,
                          const float* __restrict__ eps_g, int next_layer) {
    __shared__ float sc[DIM], sh[DIM];
    int tid = threadIdx.x;
    if (tid < DIM) {
        float mean = g_STATS[tid] * (1.0f / N_NODES);
        float var  = g_STATS[DIM + tid] * (1.0f / N_NODES) - mean * mean;
        float s    = gamma[tid] * rsqrtf(var + BN_EPS);
        sc[tid] = s;
        sh[tid] = beta[tid] - mean * s;
    }
    __syncthreads();
    float ep = 1.0f + eps_g[next_layer];
    int i = blockIdx.x * blockDim.x + tid;
    if (i < FEAT / 4) {
        float4 v = reinterpret_cast<const float4*>(g_X)[i];
        int c = (i & 15) * 4;
        v.x = fmaxf(v.x * sc[c]     + sh[c],     0.f);
        v.y = fmaxf(v.y * sc[c + 1] + sh[c + 1], 0.f);
        v.z = fmaxf(v.z * sc[c + 2] + sh[c + 2], 0.f);
        v.w = fmaxf(v.w * sc[c + 3] + sh[c + 3], 0.f);
        reinterpret_cast<float4*>(g_X)[i] = v;
        float4 a = make_float4(ep * v.x, ep * v.y, ep * v.z, ep * v.w);
        reinterpret_cast<float4*>(g_AGG)[i] = a;
    }
}

// ---------------- last layer: BN apply + relu + mean-pool accumulate ----------------
__global__ void k_bn_pool(const float* __restrict__ gamma, const float* __restrict__ beta,
                          const int* __restrict__ batch) {
    __shared__ float sc[DIM], sh[DIM];
    int tid = threadIdx.x;
    if (tid < DIM) {
        float mean = g_STATS[tid] * (1.0f / N_NODES);
        float var  = g_STATS[DIM + tid] * (1.0f / N_NODES) - mean * mean;
        float s    = gamma[tid] * rsqrtf(var + BN_EPS);
        sc[tid] = s;
        sh[tid] = beta[tid] - mean * s;
    }
    __syncthreads();
    int i = blockIdx.x * blockDim.x + tid;
    if (i < FEAT / 4) {
        int row = i >> 4;
        int g = __ldg(batch + row);
        float4 v = reinterpret_cast<const float4*>(g_X)[i];
        int c = (i & 15) * 4;
        v.x = fmaxf(v.x * sc[c]     + sh[c],     0.f);
        v.y = fmaxf(v.y * sc[c + 1] + sh[c + 1], 0.f);
        v.z = fmaxf(v.z * sc[c + 2] + sh[c + 2], 0.f);
        v.w = fmaxf(v.w * sc[c + 3] + sh[c + 3], 0.f);
        float* p = &g_POOL[g * DIM + c];
        asm volatile("red.global.add.v4.f32 [%0], {%1,%2,%3,%4};"
                     :: "l"(p), "f"(v.x), "f"(v.y), "f"(v.z), "f"(v.w) : "memory");
        if ((i & 15) == 0) atomicAdd(&g_CNT[g], 1.0f);
    }
}

// ---------------- head: out = (pool/cnt) @ lin_w + lin_b ----------------
__global__ void k_out(const float* __restrict__ lin_w, const float* __restrict__ lin_b,
                      float* __restrict__ out) {
    int gid = blockIdx.x * blockDim.x + threadIdx.x;
    if (gid < N_GRAPHS * OUT_DIM) {
        int g = gid / OUT_DIM, o = gid % OUT_DIM;
        float inv = 1.0f / fmaxf(g_CNT[g], 1.0f);
        float acc = lin_b[o];
#pragma unroll
        for (int c = 0; c < DIM; c++)
            acc += g_POOL[g * DIM + c] * inv * lin_w[c * OUT_DIM + o];
        out[gid] = acc;
    }
}

// ---------------- launch ----------------
extern "C" void kernel_launch(void* const* d_in, const int* in_sizes, int n_in,
                              void* d_out, int out_size) {
    const float* x     = (const float*)d_in[0];
    const int*   ei    = (const int*)d_in[1];
    const int*   batch = (const int*)d_in[2];
    const float* w1    = (const float*)d_in[3];
    const float* b1    = (const float*)d_in[4];
    const float* w2    = (const float*)d_in[5];
    const float* b2    = (const float*)d_in[6];
    const float* gamma = (const float*)d_in[7];
    const float* beta  = (const float*)d_in[8];
    const float* eps_g = (const float*)d_in[9];
    const float* lin_w = (const float*)d_in[10];
    const float* lin_b = (const float*)d_in[11];
    float* out = (float*)d_out;

    const int* src = ei;             // edge_index[0]
    const int* dst = ei + N_EDGES;   // edge_index[1]

    k_init<<<FEAT / 4 / 256, 256>>>((const float4*)x, eps_g);

    for (int l = 0; l < 3; l++) {
        k_scatter<<<(N_EDGES * 16) / 256, 256>>>(x, l == 0 ? 1 : 0, src, dst, l == 2 ? 1 : 0);
        k_mlp<<<(N_NODES + MLP_ROWS - 1) / MLP_ROWS, MLP_ROWS>>>(
            w1 + l * DIM * DIM, b1 + l * DIM, w2 + l * DIM * DIM, b2 + l * DIM);
        if (l < 2)
            k_bn_init<<<FEAT / 4 / 256, 256>>>(gamma + l * DIM, beta + l * DIM, eps_g, l + 1);
        else
            k_bn_pool<<<FEAT / 4 / 256, 256>>>(gamma + l * DIM, beta + l * DIM, batch);
    }

    k_out<<<(N_GRAPHS * OUT_DIM + 255) / 256, 256>>>(lin_w, lin_b, out);
}

// round 14
// speedup vs baseline: 1.0021x; 1.0013x over previous
#include <cuda_runtime.h>
#include <cstdint>

#define N_NODES 100000
#define DIM 64
#define N_EDGES 1000000
#define N_GRAPHS 256
#define OUT_DIM 10
#define FEAT (N_NODES * DIM)
#define BN_EPS 1e-5f

// ---------------- scratch (no allocation allowed) ----------------
__device__ float g_X[FEAT];            // node features between layers
__device__ float g_AGG[FEAT];          // (1+eps)*x + scatter-add target
__device__ float g_STATS[2 * DIM];     // column sums / sumsq for BN
__device__ float g_POOL[N_GRAPHS * DIM];
__device__ float g_CNT[N_GRAPHS];

// ---------------- layer 0: AGG = (1+eps0)*x ----------------
__global__ void k_init(const float4* __restrict__ x, const float* __restrict__ eps_g) {
    int i = blockIdx.x * blockDim.x + threadIdx.x;
    float ep = 1.0f + eps_g[0];
    if (i < FEAT / 4) {
        float4 v = x[i];
        v.x *= ep; v.y *= ep; v.z *= ep; v.w *= ep;
        reinterpret_cast<float4*>(g_AGG)[i] = v;
    }
}

// ---------------- scatter-add: AGG[dst] += x[src] ----------------
// 16 threads per edge, one float4 vector-red each. Also zeroes the BN stats
// (and pool buffers on the last layer) — this kernel never reads them.
__global__ void k_scatter(const float* __restrict__ xin, int use_in,
                          const int* __restrict__ src, const int* __restrict__ dst,
                          int zero_pool) {
    if (blockIdx.x == 0 && threadIdx.x < 2 * DIM) g_STATS[threadIdx.x] = 0.0f;
    if (zero_pool && blockIdx.x == 1) {
        for (int i = threadIdx.x; i < N_GRAPHS * DIM; i += blockDim.x) g_POOL[i] = 0.0f;
        for (int i = threadIdx.x; i < N_GRAPHS; i += blockDim.x) g_CNT[i] = 0.0f;
    }
    const float* x = use_in ? xin : g_X;
    int gid = blockIdx.x * blockDim.x + threadIdx.x;
    int e = gid >> 4;
    int q = gid & 15;
    if (e < N_EDGES) {
        int s = __ldg(src + e);
        int d = __ldg(dst + e);
        float4 v = *reinterpret_cast<const float4*>(x + (size_t)s * DIM + q * 4);
        float* p = g_AGG + (size_t)d * DIM + q * 4;
        asm volatile("red.global.add.v4.f32 [%0], {%1,%2,%3,%4};"
                     :: "l"(p), "f"(v.x), "f"(v.y), "f"(v.z), "f"(v.w) : "memory");
    }
}

// ---------------- fused 2x(GEMM 64x64 + bias + relu) + BN stats ----------------
// One row per thread, 64 rows per block. Inputs staged in smem (stride 65 ->
// conflict-free). Weights in smem, read as broadcast LDS.128, consumed by
// packed fma.rn.f32x2 (2 fp32 FMA / instruction).
__device__ __forceinline__ void gemm_row(const float* __restrict__ in_row,
                                         const ulonglong2* __restrict__ wp,
                                         const float* __restrict__ bias,
                                         unsigned long long acc[32]) {
#pragma unroll
    for (int j = 0; j < 32; j++)
        asm("mov.b64 %0, {%1,%2};" : "=l"(acc[j]) : "f"(bias[2 * j]), "f"(bias[2 * j + 1]));
#pragma unroll 4
    for (int k = 0; k < DIM; k++) {
        float v = in_row[k];
        unsigned long long vv;
        asm("mov.b64 %0, {%1,%1};" : "=l"(vv) : "f"(v));
#pragma unroll
        for (int q = 0; q < 16; q++) {
            ulonglong2 w = wp[k * 16 + q];
            asm("fma.rn.f32x2 %0, %1, %2, %0;" : "+l"(acc[2 * q])     : "l"(vv), "l"(w.x));
            asm("fma.rn.f32x2 %0, %1, %2, %0;" : "+l"(acc[2 * q + 1]) : "l"(vv), "l"(w.y));
        }
    }
}

#define MLP_ROWS 64
#define SPITCH (DIM + 1)

__global__ __launch_bounds__(MLP_ROWS)
void k_mlp(const float* __restrict__ w1, const float* __restrict__ b1,
           const float* __restrict__ w2, const float* __restrict__ b2) {
    __shared__ float  s_in[MLP_ROWS * SPITCH];
    __shared__ float4 s_w[DIM * DIM / 4];
    __shared__ float  s_b[DIM];

    int tid  = threadIdx.x;
    int base = blockIdx.x * MLP_ROWS;
    int row  = base + tid;

    // stage 64 input rows (coalesced float4 loads)
    for (int i = tid; i < MLP_ROWS * DIM / 4; i += MLP_ROWS) {
        int r = i >> 4, c4 = i & 15;
        float4 v = (base + r < N_NODES)
                       ? reinterpret_cast<const float4*>(g_AGG)[(size_t)base * 16 + i]
                       : make_float4(0.f, 0.f, 0.f, 0.f);
        float* p = &s_in[r * SPITCH + c4 * 4];
        p[0] = v.x; p[1] = v.y; p[2] = v.z; p[3] = v.w;
    }
    for (int i = tid; i < DIM * DIM / 4; i += MLP_ROWS)
        s_w[i] = reinterpret_cast<const float4*>(w1)[i];
    if (tid < DIM) s_b[tid] = b1[tid];
    __syncthreads();

    unsigned long long acc[32];
    const ulonglong2* wp = reinterpret_cast<const ulonglong2*>(s_w);

    // GEMM1 + relu -> own smem row (only this thread touches its row)
    gemm_row(&s_in[tid * SPITCH], wp, s_b, acc);
#pragma unroll
    for (int j = 0; j < 32; j++) {
        float lo, hi;
        asm("mov.b64 {%0,%1}, %2;" : "=f"(lo), "=f"(hi) : "l"(acc[j]));
        s_in[tid * SPITCH + 2 * j]     = fmaxf(lo, 0.f);
        s_in[tid * SPITCH + 2 * j + 1] = fmaxf(hi, 0.f);
    }
    __syncthreads();  // everyone done with w1 before overwrite

    for (int i = tid; i < DIM * DIM / 4; i += MLP_ROWS)
        s_w[i] = reinterpret_cast<const float4*>(w2)[i];
    if (tid < DIM) s_b[tid] = b2[tid];
    __syncthreads();

    // GEMM2 + relu; invalid rows must contribute exact zeros to BN stats
    gemm_row(&s_in[tid * SPITCH], wp, s_b, acc);
    bool valid = (row < N_NODES);
#pragma unroll
    for (int j = 0; j < 32; j++) {
        float lo, hi;
        asm("mov.b64 {%0,%1}, %2;" : "=f"(lo), "=f"(hi) : "l"(acc[j]));
        s_in[tid * SPITCH + 2 * j]     = valid ? fmaxf(lo, 0.f) : 0.f;
        s_in[tid * SPITCH + 2 * j + 1] = valid ? fmaxf(hi, 0.f) : 0.f;
    }
    __syncthreads();

    // coalesced writeback of h2
    for (int i = tid; i < MLP_ROWS * DIM / 4; i += MLP_ROWS) {
        int r = i >> 4, c4 = i & 15;
        if (base + r < N_NODES) {
            float* p = &s_in[r * SPITCH + c4 * 4];
            reinterpret_cast<float4*>(g_X)[(size_t)base * 16 + i] =
                make_float4(p[0], p[1], p[2], p[3]);
        }
    }

    // BN partial stats: thread tid owns column tid
    float s = 0.f, s2 = 0.f;
#pragma unroll 8
    for (int r = 0; r < MLP_ROWS; r++) {
        float v = s_in[r * SPITCH + tid];
        s += v; s2 += v * v;
    }
    atomicAdd(&g_STATS[tid], s);
    atomicAdd(&g_STATS[DIM + tid], s2);
}

// ---------------- BN apply + relu + next-layer (1+eps)*x init ----------------
__global__ void k_bn_init(const float* __restrict__ gamma, const float* __restrict__ beta,
                          const float* __restrict__ eps_g, int next_layer) {
    __shared__ float sc[DIM], sh[DIM];
    int tid = threadIdx.x;
    if (tid < DIM) {
        float mean = g_STATS[tid] * (1.0f / N_NODES);
        float var  = g_STATS[DIM + tid] * (1.0f / N_NODES) - mean * mean;
        float s    = gamma[tid] * rsqrtf(var + BN_EPS);
        sc[tid] = s;
        sh[tid] = beta[tid] - mean * s;
    }
    __syncthreads();
    float ep = 1.0f + eps_g[next_layer];
    int i = blockIdx.x * blockDim.x + tid;
    if (i < FEAT / 4) {
        float4 v = reinterpret_cast<const float4*>(g_X)[i];
        int c = (i & 15) * 4;
        v.x = fmaxf(v.x * sc[c]     + sh[c],     0.f);
        v.y = fmaxf(v.y * sc[c + 1] + sh[c + 1], 0.f);
        v.z = fmaxf(v.z * sc[c + 2] + sh[c + 2], 0.f);
        v.w = fmaxf(v.w * sc[c + 3] + sh[c + 3], 0.f);
        reinterpret_cast<float4*>(g_X)[i] = v;
        float4 a = make_float4(ep * v.x, ep * v.y, ep * v.z, ep * v.w);
        reinterpret_cast<float4*>(g_AGG)[i] = a;
    }
}

// ---------------- last layer: BN apply + relu + mean-pool accumulate ----------------
__global__ void k_bn_pool(const float* __restrict__ gamma, const float* __restrict__ beta,
                          const int* __restrict__ batch) {
    __shared__ float sc[DIM], sh[DIM];
    int tid = threadIdx.x;
    if (tid < DIM) {
        float mean = g_STATS[tid] * (1.0f / N_NODES);
        float var  = g_STATS[DIM + tid] * (1.0f / N_NODES) - mean * mean;
        float s    = gamma[tid] * rsqrtf(var + BN_EPS);
        sc[tid] = s;
        sh[tid] = beta[tid] - mean * s;
    }
    __syncthreads();
    int i = blockIdx.x * blockDim.x + tid;
    if (i < FEAT / 4) {
        int row = i >> 4;
        int g = __ldg(batch + row);
        float4 v = reinterpret_cast<const float4*>(g_X)[i];
        int c = (i & 15) * 4;
        v.x = fmaxf(v.x * sc[c]     + sh[c],     0.f);
        v.y = fmaxf(v.y * sc[c + 1] + sh[c + 1], 0.f);
        v.z = fmaxf(v.z * sc[c + 2] + sh[c + 2], 0.f);
        v.w = fmaxf(v.w * sc[c + 3] + sh[c + 3], 0.f);
        float* p = &g_POOL[g * DIM + c];
        asm volatile("red.global.add.v4.f32 [%0], {%1,%2,%3,%4};"
                     :: "l"(p), "f"(v.x), "f"(v.y), "f"(v.z), "f"(v.w) : "memory");
        if ((i & 15) == 0) atomicAdd(&g_CNT[g], 1.0f);
    }
}

// ---------------- head: out = (pool/cnt) @ lin_w + lin_b ----------------
__global__ void k_out(const float* __restrict__ lin_w, const float* __restrict__ lin_b,
                      float* __restrict__ out) {
    int gid = blockIdx.x * blockDim.x + threadIdx.x;
    if (gid < N_GRAPHS * OUT_DIM) {
        int g = gid / OUT_DIM, o = gid % OUT_DIM;
        float inv = 1.0f / fmaxf(g_CNT[g], 1.0f);
        float acc = lin_b[o];
#pragma unroll
        for (int c = 0; c < DIM; c++)
            acc += g_POOL[g * DIM + c] * inv * lin_w[c * OUT_DIM + o];
        out[gid] = acc;
    }
}

// ---------------- launch ----------------
extern "C" void kernel_launch(void* const* d_in, const int* in_sizes, int n_in,
                              void* d_out, int out_size) {
    const float* x     = (const float*)d_in[0];
    const int*   ei    = (const int*)d_in[1];
    const int*   batch = (const int*)d_in[2];
    const float* w1    = (const float*)d_in[3];
    const float* b1    = (const float*)d_in[4];
    const float* w2    = (const float*)d_in[5];
    const float* b2    = (const float*)d_in[6];
    const float* gamma = (const float*)d_in[7];
    const float* beta  = (const float*)d_in[8];
    const float* eps_g = (const float*)d_in[9];
    const float* lin_w = (const float*)d_in[10];
    const float* lin_b = (const float*)d_in[11];
    float* out = (float*)d_out;

    const int* src = ei;             // edge_index[0]
    const int* dst = ei + N_EDGES;   // edge_index[1]

    k_init<<<FEAT / 4 / 256, 256>>>((const float4*)x, eps_g);

    for (int l = 0; l < 3; l++) {
        k_scatter<<<(N_EDGES * 16) / 256, 256>>>(x, l == 0 ? 1 : 0, src, dst, l == 2 ? 1 : 0);
        k_mlp<<<(N_NODES + MLP_ROWS - 1) / MLP_ROWS, MLP_ROWS>>>(
            w1 + l * DIM * DIM, b1 + l * DIM, w2 + l * DIM * DIM, b2 + l * DIM);
        if (l < 2)
            k_bn_init<<<FEAT / 4 / 256, 256>>>(gamma + l * DIM, beta + l * DIM, eps_g, l + 1);
        else
            k_bn_pool<<<FEAT / 4 / 256, 256>>>(gamma + l * DIM, beta + l * DIM, batch);
    }

    k_out<<<(N_GRAPHS * OUT_DIM + 255) / 256, 256>>>(lin_w, lin_b, out);
}

// round 15
// speedup vs baseline: 1.0065x; 1.0044x over previous
#include <cuda_runtime.h>
#include <cstdint>

#define N_NODES 100000
#define DIM 64
#define N_EDGES 1000000
#define N_GRAPHS 256
#define OUT_DIM 10
#define FEAT (N_NODES * DIM)
#define BN_EPS 1e-5f

// ---------------- scratch (no allocation allowed) ----------------
__device__ float g_X[FEAT];            // node features between layers
__device__ float g_AGG[FEAT];          // (1+eps)*x + scatter-add target
__device__ float g_STATS[2 * DIM];     // column sums / sumsq for BN
__device__ float g_POOL[N_GRAPHS * DIM];
__device__ float g_CNT[N_GRAPHS];

// ---------------- layer 0: AGG = (1+eps0)*x ----------------
__global__ void k_init(const float4* __restrict__ x, const float* __restrict__ eps_g) {
    int i = blockIdx.x * blockDim.x + threadIdx.x;
    float ep = 1.0f + eps_g[0];
    if (i < FEAT / 4) {
        float4 v = x[i];
        v.x *= ep; v.y *= ep; v.z *= ep; v.w *= ep;
        reinterpret_cast<float4*>(g_AGG)[i] = v;
    }
}

// ---------------- scatter-add: AGG[dst] += x[src] ----------------
// 16 threads per edge, one float4 vector-red each. Also zeroes the BN stats
// (and pool buffers on the last layer) — this kernel never reads them.
__global__ void k_scatter(const float* __restrict__ xin, int use_in,
                          const int* __restrict__ src, const int* __restrict__ dst,
                          int zero_pool) {
    if (blockIdx.x == 0 && threadIdx.x < 2 * DIM) g_STATS[threadIdx.x] = 0.0f;
    if (zero_pool && blockIdx.x == 1) {
        for (int i = threadIdx.x; i < N_GRAPHS * DIM; i += blockDim.x) g_POOL[i] = 0.0f;
        for (int i = threadIdx.x; i < N_GRAPHS; i += blockDim.x) g_CNT[i] = 0.0f;
    }
    const float* x = use_in ? xin : g_X;
    int gid = blockIdx.x * blockDim.x + threadIdx.x;
    int e = gid >> 4;
    int q = gid & 15;
    if (e < N_EDGES) {
        int s = __ldg(src + e);
        int d = __ldg(dst + e);
        float4 v = *reinterpret_cast<const float4*>(x + (size_t)s * DIM + q * 4);
        float* p = g_AGG + (size_t)d * DIM + q * 4;
        asm volatile("red.global.add.v4.f32 [%0], {%1,%2,%3,%4};"
                     :: "l"(p), "f"(v.x), "f"(v.y), "f"(v.z), "f"(v.w) : "memory");
    }
}

// ---------------- fused 2x(GEMM 64x64 + bias + relu) + BN stats ----------------
// One row per thread, 64 rows per block. Inputs staged in smem (stride 65 ->
// conflict-free). Weights in smem, read as broadcast LDS.128, consumed by
// packed fma.rn.f32x2 (2 fp32 FMA / instruction).
__device__ __forceinline__ void gemm_row(const float* __restrict__ in_row,
                                         const ulonglong2* __restrict__ wp,
                                         const float* __restrict__ bias,
                                         unsigned long long acc[32]) {
#pragma unroll
    for (int j = 0; j < 32; j++)
        asm("mov.b64 %0, {%1,%2};" : "=l"(acc[j]) : "f"(bias[2 * j]), "f"(bias[2 * j + 1]));
#pragma unroll 4
    for (int k = 0; k < DIM; k++) {
        float v = in_row[k];
        unsigned long long vv;
        asm("mov.b64 %0, {%1,%1};" : "=l"(vv) : "f"(v));
#pragma unroll
        for (int q = 0; q < 16; q++) {
            ulonglong2 w = wp[k * 16 + q];
            asm("fma.rn.f32x2 %0, %1, %2, %0;" : "+l"(acc[2 * q])     : "l"(vv), "l"(w.x));
            asm("fma.rn.f32x2 %0, %1, %2, %0;" : "+l"(acc[2 * q + 1]) : "l"(vv), "l"(w.y));
        }
    }
}

#define MLP_ROWS 64
#define SPITCH (DIM + 1)

__global__ __launch_bounds__(MLP_ROWS)
void k_mlp(const float* __restrict__ w1, const float* __restrict__ b1,
           const float* __restrict__ w2, const float* __restrict__ b2) {
    __shared__ float  s_in[MLP_ROWS * SPITCH];
    __shared__ float4 s_w[DIM * DIM / 4];
    __shared__ float  s_b[DIM];

    int tid  = threadIdx.x;
    int base = blockIdx.x * MLP_ROWS;
    int row  = base + tid;

    // stage 64 input rows (coalesced float4 loads)
    for (int i = tid; i < MLP_ROWS * DIM / 4; i += MLP_ROWS) {
        int r = i >> 4, c4 = i & 15;
        float4 v = (base + r < N_NODES)
                       ? reinterpret_cast<const float4*>(g_AGG)[(size_t)base * 16 + i]
                       : make_float4(0.f, 0.f, 0.f, 0.f);
        float* p = &s_in[r * SPITCH + c4 * 4];
        p[0] = v.x; p[1] = v.y; p[2] = v.z; p[3] = v.w;
    }
    for (int i = tid; i < DIM * DIM / 4; i += MLP_ROWS)
        s_w[i] = reinterpret_cast<const float4*>(w1)[i];
    if (tid < DIM) s_b[tid] = b1[tid];
    __syncthreads();

    unsigned long long acc[32];
    const ulonglong2* wp = reinterpret_cast<const ulonglong2*>(s_w);

    // GEMM1 + relu -> own smem row (only this thread touches its row)
    gemm_row(&s_in[tid * SPITCH], wp, s_b, acc);
#pragma unroll
    for (int j = 0; j < 32; j++) {
        float lo, hi;
        asm("mov.b64 {%0,%1}, %2;" : "=f"(lo), "=f"(hi) : "l"(acc[j]));
        s_in[tid * SPITCH + 2 * j]     = fmaxf(lo, 0.f);
        s_in[tid * SPITCH + 2 * j + 1] = fmaxf(hi, 0.f);
    }
    __syncthreads();  // everyone done with w1 before overwrite

    for (int i = tid; i < DIM * DIM / 4; i += MLP_ROWS)
        s_w[i] = reinterpret_cast<const float4*>(w2)[i];
    if (tid < DIM) s_b[tid] = b2[tid];
    __syncthreads();

    // GEMM2 + relu; invalid rows must contribute exact zeros to BN stats
    gemm_row(&s_in[tid * SPITCH], wp, s_b, acc);
    bool valid = (row < N_NODES);
#pragma unroll
    for (int j = 0; j < 32; j++) {
        float lo, hi;
        asm("mov.b64 {%0,%1}, %2;" : "=f"(lo), "=f"(hi) : "l"(acc[j]));
        s_in[tid * SPITCH + 2 * j]     = valid ? fmaxf(lo, 0.f) : 0.f;
        s_in[tid * SPITCH + 2 * j + 1] = valid ? fmaxf(hi, 0.f) : 0.f;
    }
    __syncthreads();

    // coalesced writeback of h2
    for (int i = tid; i < MLP_ROWS * DIM / 4; i += MLP_ROWS) {
        int r = i >> 4, c4 = i & 15;
        if (base + r < N_NODES) {
            float* p = &s_in[r * SPITCH + c4 * 4];
            reinterpret_cast<float4*>(g_X)[(size_t)base * 16 + i] =
                make_float4(p[0], p[1], p[2], p[3]);
        }
    }

    // BN partial stats: thread tid owns column tid
    float s = 0.f, s2 = 0.f;
#pragma unroll 8
    for (int r = 0; r < MLP_ROWS; r++) {
        float v = s_in[r * SPITCH + tid];
        s += v; s2 += v * v;
    }
    atomicAdd(&g_STATS[tid], s);
    atomicAdd(&g_STATS[DIM + tid], s2);
}

// ---------------- BN apply + relu + next-layer (1+eps)*x init ----------------
__global__ void k_bn_init(const float* __restrict__ gamma, const float* __restrict__ beta,
                          const float* __restrict__ eps_g, int next_layer) {
    __shared__ float sc[DIM], sh[DIM];
    int tid = threadIdx.x;
    if (tid < DIM) {
        float mean = g_STATS[tid] * (1.0f / N_NODES);
        float var  = g_STATS[DIM + tid] * (1.0f / N_NODES) - mean * mean;
        float s    = gamma[tid] * rsqrtf(var + BN_EPS);
        sc[tid] = s;
        sh[tid] = beta[tid] - mean * s;
    }
    __syncthreads();
    float ep = 1.0f + eps_g[next_layer];
    int i = blockIdx.x * blockDim.x + tid;
    if (i < FEAT / 4) {
        float4 v = reinterpret_cast<const float4*>(g_X)[i];
        int c = (i & 15) * 4;
        v.x = fmaxf(v.x * sc[c]     + sh[c],     0.f);
        v.y = fmaxf(v.y * sc[c + 1] + sh[c + 1], 0.f);
        v.z = fmaxf(v.z * sc[c + 2] + sh[c + 2], 0.f);
        v.w = fmaxf(v.w * sc[c + 3] + sh[c + 3], 0.f);
        reinterpret_cast<float4*>(g_X)[i] = v;
        float4 a = make_float4(ep * v.x, ep * v.y, ep * v.z, ep * v.w);
        reinterpret_cast<float4*>(g_AGG)[i] = a;
    }
}

// ---------------- last layer: BN apply + relu + mean-pool accumulate ----------------
__global__ void k_bn_pool(const float* __restrict__ gamma, const float* __restrict__ beta,
                          const int* __restrict__ batch) {
    __shared__ float sc[DIM], sh[DIM];
    int tid = threadIdx.x;
    if (tid < DIM) {
        float mean = g_STATS[tid] * (1.0f / N_NODES);
        float var  = g_STATS[DIM + tid] * (1.0f / N_NODES) - mean * mean;
        float s    = gamma[tid] * rsqrtf(var + BN_EPS);
        sc[tid] = s;
        sh[tid] = beta[tid] - mean * s;
    }
    __syncthreads();
    int i = blockIdx.x * blockDim.x + tid;
    if (i < FEAT / 4) {
        int row = i >> 4;
        int g = __ldg(batch + row);
        float4 v = reinterpret_cast<const float4*>(g_X)[i];
        int c = (i & 15) * 4;
        v.x = fmaxf(v.x * sc[c]     + sh[c],     0.f);
        v.y = fmaxf(v.y * sc[c + 1] + sh[c + 1], 0.f);
        v.z = fmaxf(v.z * sc[c + 2] + sh[c + 2], 0.f);
        v.w = fmaxf(v.w * sc[c + 3] + sh[c + 3], 0.f);
        float* p = &g_POOL[g * DIM + c];
        asm volatile("red.global.add.v4.f32 [%0], {%1,%2,%3,%4};"
                     :: "l"(p), "f"(v.x), "f"(v.y), "f"(v.z), "f"(v.w) : "memory");
        if ((i & 15) == 0) atomicAdd(&g_CNT[g], 1.0f);
    }
}

// ---------------- head: out = (pool/cnt) @ lin_w + lin_b ----------------
__global__ void k_out(const float* __restrict__ lin_w, const float* __restrict__ lin_b,
                      float* __restrict__ out) {
    int gid = blockIdx.x * blockDim.x + threadIdx.x;
    if (gid < N_GRAPHS * OUT_DIM) {
        int g = gid / OUT_DIM, o = gid % OUT_DIM;
        float inv = 1.0f / fmaxf(g_CNT[g], 1.0f);
        float acc = lin_b[o];
#pragma unroll
        for (int c = 0; c < DIM; c++)
            acc += g_POOL[g * DIM + c] * inv * lin_w[c * OUT_DIM + o];
        out[gid] = acc;
    }
}

// ---------------- launch ----------------
extern "C" void kernel_launch(void* const* d_in, const int* in_sizes, int n_in,
                              void* d_out, int out_size) {
    const float* x     = (const float*)d_in[0];
    const int*   ei    = (const int*)d_in[1];
    const int*   batch = (const int*)d_in[2];
    const float* w1    = (const float*)d_in[3];
    const float* b1    = (const float*)d_in[4];
    const float* w2    = (const float*)d_in[5];
    const float* b2    = (const float*)d_in[6];
    const float* gamma = (const float*)d_in[7];
    const float* beta  = (const float*)d_in[8];
    const float* eps_g = (const float*)d_in[9];
    const float* lin_w = (const float*)d_in[10];
    const float* lin_b = (const float*)d_in[11];
    float* out = (float*)d_out;

    const int* src = ei;             // edge_index[0]
    const int* dst = ei + N_EDGES;   // edge_index[1]

    k_init<<<FEAT / 4 / 256, 256>>>((const float4*)x, eps_g);

    for (int l = 0; l < 3; l++) {
        k_scatter<<<(N_EDGES * 16) / 256, 256>>>(x, l == 0 ? 1 : 0, src, dst, l == 2 ? 1 : 0);
        k_mlp<<<(N_NODES + MLP_ROWS - 1) / MLP_ROWS, MLP_ROWS>>>(
            w1 + l * DIM * DIM, b1 + l * DIM, w2 + l * DIM * DIM, b2 + l * DIM);
        if (l < 2)
            k_bn_init<<<FEAT / 4 / 256, 256>>>(gamma + l * DIM, beta + l * DIM, eps_g, l + 1);
        else
            k_bn_pool<<<FEAT / 4 / 256, 256>>>(gamma + l * DIM, beta + l * DIM, batch);
    }

    k_out<<<(N_GRAPHS * OUT_DIM + 255) / 256, 256>>>(lin_w, lin_b, out);
}